// round 9
// baseline (speedup 1.0000x reference)
#include <cuda_runtime.h>

#define B_ 4
#define S_ 4096
#define D_ 1024
#define H_ 64

// Scratch: Q and K stored transposed [B][H][S] for conflict-free attention tiles,
// V stored natural [B][S][H].
__device__ float g_qt[B_ * H_ * S_];
__device__ float g_kt[B_ * H_ * S_];
__device__ float g_v [B_ * S_ * H_];

__device__ __forceinline__ void fma4x4(float (&acc)[4][4], const float4 a, const float4 b)
{
    acc[0][0] += a.x * b.x; acc[0][1] += a.x * b.y; acc[0][2] += a.x * b.z; acc[0][3] += a.x * b.w;
    acc[1][0] += a.y * b.x; acc[1][1] += a.y * b.y; acc[1][2] += a.y * b.z; acc[1][3] += a.y * b.w;
    acc[2][0] += a.z * b.x; acc[2][1] += a.z * b.y; acc[2][2] += a.z * b.z; acc[2][3] += a.z * b.w;
    acc[3][0] += a.w * b.x; acc[3][1] += a.w * b.y; acc[3][2] += a.w * b.z; acc[3][3] += a.w * b.w;
}

// ---------------------------------------------------------------------------
// QKV projection: out[m][h] = sum_d x[m][d] * w[h][d] + bias[h]
// M = B*S = 16384, K = 1024, N = 64. blockIdx.z selects {Q, K, V}.
// Q and K are written transposed to [B][H][S]; V natural [B][S][H].
// BM=64, BN=64, BK=16, 256 threads, 4x4 micro-tile.
// ---------------------------------------------------------------------------
__global__ __launch_bounds__(256) void qkv_proj(
    const float* __restrict__ x,
    const float* __restrict__ wq, const float* __restrict__ bq,
    const float* __restrict__ wk, const float* __restrict__ bk,
    const float* __restrict__ wv, const float* __restrict__ bv)
{
    __shared__ float xs[16][68];   // [k][m], pad 68 to soften transpose-write conflicts
    __shared__ float ws[16][68];   // [k][n]

    const float* w; const float* bias; float* out; int trans;
    switch (blockIdx.z) {
        case 0:  w = wq; bias = bq; out = g_qt; trans = 1; break;
        case 1:  w = wk; bias = bk; out = g_kt; trans = 1; break;
        default: w = wv; bias = bv; out = g_v;  trans = 0; break;
    }

    const int tid = threadIdx.x;
    const int tx = tid & 15;
    const int ty = tid >> 4;
    const int lm = tid >> 2;          // 0..63 : row within tile (m or n)
    const int lk = (tid & 3) << 2;    // 0,4,8,12 : k sub-offset
    const int m0 = blockIdx.x * 64;

    float acc[4][4] = {};

    for (int k0 = 0; k0 < D_; k0 += 16) {
        __syncthreads();
        float4 xv = *(const float4*)&x[(m0 + lm) * D_ + k0 + lk];
        xs[lk + 0][lm] = xv.x; xs[lk + 1][lm] = xv.y;
        xs[lk + 2][lm] = xv.z; xs[lk + 3][lm] = xv.w;
        float4 wv4 = *(const float4*)&w[lm * D_ + k0 + lk];
        ws[lk + 0][lm] = wv4.x; ws[lk + 1][lm] = wv4.y;
        ws[lk + 2][lm] = wv4.z; ws[lk + 3][lm] = wv4.w;
        __syncthreads();

        #pragma unroll
        for (int kk = 0; kk < 16; kk++) {
            float4 a = *(const float4*)&xs[kk][ty * 4];
            float4 b = *(const float4*)&ws[kk][tx * 4];
            fma4x4(acc, a, b);
        }
    }

    const int bb = m0 / S_;
    const int s0 = m0 % S_;
    if (trans) {
        // out[(b*H + h)*S + s], thread owns 4 consecutive s (i) per h column (j)
        #pragma unroll
        for (int j = 0; j < 4; j++) {
            int h = tx * 4 + j;
            float bv_ = bias[h];
            float4 v = make_float4(acc[0][j] + bv_, acc[1][j] + bv_,
                                   acc[2][j] + bv_, acc[3][j] + bv_);
            *(float4*)&out[(bb * H_ + h) * S_ + s0 + ty * 4] = v;
        }
    } else {
        float4 b4 = *(const float4*)&bias[tx * 4];
        #pragma unroll
        for (int i = 0; i < 4; i++) {
            float4 v = make_float4(acc[i][0] + b4.x, acc[i][1] + b4.y,
                                   acc[i][2] + b4.z, acc[i][3] + b4.w);
            *(float4*)&out[(m0 + ty * 4 + i) * H_ + tx * 4] = v;
        }
    }
}

// ---------------------------------------------------------------------------
// Flash attention, causal, fp32. One CTA handles query tiles x and 63-x of
// one batch (uniform 65 key-tiles of work per CTA). BM=BN=HD=64, 256 threads,
// 4x4 micro-tiles for both GEMMs, online softmax with 16-lane shuffle
// reductions. ps aliases ks (live ranges disjoint) -> exactly 48KB static smem.
// ---------------------------------------------------------------------------
__global__ __launch_bounds__(256) void attn_kernel(float* __restrict__ out)
{
    __shared__ float qs[64][64];   // [d][q]  (Q^T tile, pre-scaled by 1/sqrt(HD))
    __shared__ float ks[64][64];   // [d][k]  (K^T tile); reused as ps[q][k]
    __shared__ float vs[64][64];   // [k][h]
    float (*ps)[64] = ks;

    const int b   = blockIdx.y;
    const int tid = threadIdx.x;
    const int tx  = tid & 15;
    const int ty  = tid >> 4;
    const int lq  = tx * 4;    // column offset for cooperative float4 loads
    const int lh  = ty;        // row base for cooperative loads (stride 16)

    for (int half = 0; half < 2; half++) {
        const int qt = half ? (63 - (int)blockIdx.x) : (int)blockIdx.x;

        __syncthreads();   // protect qs against previous half's readers
        #pragma unroll
        for (int r = 0; r < 4; r++) {
            int h = lh + r * 16;
            float4 v = *(const float4*)&g_qt[(b * H_ + h) * S_ + qt * 64 + lq];
            v.x *= 0.125f; v.y *= 0.125f; v.z *= 0.125f; v.w *= 0.125f;
            *(float4*)&qs[h][lq] = v;
        }

        float o[4][4] = {};
        float m[4], l[4];
        #pragma unroll
        for (int i = 0; i < 4; i++) { m[i] = -3.0e38f; l[i] = 0.0f; }

        for (int kt = 0; kt <= qt; kt++) {
            __syncthreads();   // previous iteration's PV GEMM finished
            #pragma unroll
            for (int r = 0; r < 4; r++) {
                int h = lh + r * 16;
                *(float4*)&ks[h][lq] =
                    *(const float4*)&g_kt[(b * H_ + h) * S_ + kt * 64 + lq];
                *(float4*)&vs[h][lq] =
                    *(const float4*)&g_v[((b * S_) + kt * 64 + h) * H_ + lq];
            }
            __syncthreads();

            // GEMM1: s[i][j] = sum_d qs[d][ty*4+i] * ks[d][tx*4+j]
            float s[4][4] = {};
            #pragma unroll 16
            for (int d = 0; d < 64; d++) {
                float4 a  = *(const float4*)&qs[d][ty * 4];
                float4 kb = *(const float4*)&ks[d][lq];
                fma4x4(s, a, kb);
            }

            if (kt == qt) {   // causal mask within diagonal tile
                #pragma unroll
                for (int i = 0; i < 4; i++)
                    #pragma unroll
                    for (int j = 0; j < 4; j++)
                        if (lq + j > ty * 4 + i) s[i][j] = -1.0e30f;
            }

            __syncthreads();   // all threads done reading ks -> safe to reuse as ps

            // online softmax update + write P tile
            #pragma unroll
            for (int i = 0; i < 4; i++) {
                float mt = fmaxf(fmaxf(s[i][0], s[i][1]), fmaxf(s[i][2], s[i][3]));
                mt = fmaxf(mt, __shfl_xor_sync(0xffffffffu, mt, 1));
                mt = fmaxf(mt, __shfl_xor_sync(0xffffffffu, mt, 2));
                mt = fmaxf(mt, __shfl_xor_sync(0xffffffffu, mt, 4));
                mt = fmaxf(mt, __shfl_xor_sync(0xffffffffu, mt, 8));
                float mnew  = fmaxf(m[i], mt);
                float alpha = __expf(m[i] - mnew);
                m[i] = mnew;
                float rs = 0.0f;
                #pragma unroll
                for (int j = 0; j < 4; j++) {
                    float p = __expf(s[i][j] - mnew);
                    s[i][j] = p;
                    rs += p;
                }
                rs += __shfl_xor_sync(0xffffffffu, rs, 1);
                rs += __shfl_xor_sync(0xffffffffu, rs, 2);
                rs += __shfl_xor_sync(0xffffffffu, rs, 4);
                rs += __shfl_xor_sync(0xffffffffu, rs, 8);
                l[i] = l[i] * alpha + rs;
                #pragma unroll
                for (int j = 0; j < 4; j++) o[i][j] *= alpha;
                *(float4*)&ps[ty * 4 + i][lq] =
                    make_float4(s[i][0], s[i][1], s[i][2], s[i][3]);
            }
            __syncthreads();

            // GEMM2: o[i][j] += sum_k ps[ty*4+i][k] * vs[k][tx*4+j]
            #pragma unroll 16
            for (int kk = 0; kk < 64; kk++) {
                float a0 = ps[ty * 4 + 0][kk];
                float a1 = ps[ty * 4 + 1][kk];
                float a2 = ps[ty * 4 + 2][kk];
                float a3 = ps[ty * 4 + 3][kk];
                float4 vv = *(const float4*)&vs[kk][lq];
                o[0][0] += a0 * vv.x; o[0][1] += a0 * vv.y; o[0][2] += a0 * vv.z; o[0][3] += a0 * vv.w;
                o[1][0] += a1 * vv.x; o[1][1] += a1 * vv.y; o[1][2] += a1 * vv.z; o[1][3] += a1 * vv.w;
                o[2][0] += a2 * vv.x; o[2][1] += a2 * vv.y; o[2][2] += a2 * vv.z; o[2][3] += a2 * vv.w;
                o[3][0] += a3 * vv.x; o[3][1] += a3 * vv.y; o[3][2] += a3 * vv.z; o[3][3] += a3 * vv.w;
            }
        }

        #pragma unroll
        for (int i = 0; i < 4; i++) {
            float inv = 1.0f / l[i];
            float4 v = make_float4(o[i][0] * inv, o[i][1] * inv,
                                   o[i][2] * inv, o[i][3] * inv);
            *(float4*)&out[((b * S_) + qt * 64 + ty * 4 + i) * H_ + lq] = v;
        }
    }
}

extern "C" void kernel_launch(void* const* d_in, const int* in_sizes, int n_in,
                              void* d_out, int out_size)
{
    (void)in_sizes; (void)n_in; (void)out_size;
    const float* x  = (const float*)d_in[0];
    const float* wq = (const float*)d_in[1];
    const float* bq = (const float*)d_in[2];
    const float* wk = (const float*)d_in[3];
    const float* bk = (const float*)d_in[4];
    const float* wv = (const float*)d_in[5];
    const float* bv = (const float*)d_in[6];
    float* out = (float*)d_out;

    qkv_proj<<<dim3((B_ * S_) / 64, 1, 3), 256>>>(x, wq, bq, wk, bk, wv, bv);
    attn_kernel<<<dim3(32, B_), 256>>>(out);
}

// round 10
// speedup vs baseline: 1.1667x; 1.1667x over previous
#include <cuda_runtime.h>

#define B_ 4
#define S_ 4096
#define D_ 1024
#define H_ 64

// Scratch: Q and K stored transposed [B][H][S], V natural [B][S][H].
__device__ float g_qt[B_ * H_ * S_];
__device__ float g_kt[B_ * H_ * S_];
__device__ float g_v [B_ * S_ * H_];
// Split-K attention partials: j in {0,1} handles kt ≡ j (mod 2).
__device__ float g_op[2 * B_ * S_ * H_];   // unnormalized O partials
__device__ float g_mp[2 * B_ * S_];        // row max partials
__device__ float g_lp[2 * B_ * S_];        // row sum partials

__device__ __forceinline__ void fma4x4(float (&acc)[4][4], const float4 a, const float4 b)
{
    acc[0][0] += a.x * b.x; acc[0][1] += a.x * b.y; acc[0][2] += a.x * b.z; acc[0][3] += a.x * b.w;
    acc[1][0] += a.y * b.x; acc[1][1] += a.y * b.y; acc[1][2] += a.y * b.z; acc[1][3] += a.y * b.w;
    acc[2][0] += a.z * b.x; acc[2][1] += a.z * b.y; acc[2][2] += a.z * b.z; acc[2][3] += a.z * b.w;
    acc[3][0] += a.w * b.x; acc[3][1] += a.w * b.y; acc[3][2] += a.w * b.z; acc[3][3] += a.w * b.w;
}

// ---------------------------------------------------------------------------
// Fused QKV projection: all three GEMMs in one kernel, x tile read ONCE.
// out[m][h] = sum_d x[m][d]*w[h][d] + b[h], for w in {wq, wk, wv}.
// BM=64, N=3x64, BK=16, 256 threads, per-thread micro-tile 4x(3x4).
// Q,K written transposed [B][H][S]; V natural [B][S][H].
// ---------------------------------------------------------------------------
__global__ __launch_bounds__(256) void qkv_proj_fused(
    const float* __restrict__ x,
    const float* __restrict__ wq, const float* __restrict__ bq,
    const float* __restrict__ wk, const float* __restrict__ bk,
    const float* __restrict__ wv, const float* __restrict__ bv)
{
    __shared__ float xs[16][68];       // [k][m]
    __shared__ float ws[3][16][68];    // [mat][k][h]

    const int tid = threadIdx.x;
    const int tx = tid & 15;
    const int ty = tid >> 4;
    const int lm = tid >> 2;           // 0..63
    const int lk = (tid & 3) << 2;     // 0,4,8,12
    const int m0 = blockIdx.x * 64;

    const float* wp[3] = { wq, wk, wv };
    float acc[3][4][4] = {};

    for (int k0 = 0; k0 < D_; k0 += 16) {
        __syncthreads();
        float4 xv = *(const float4*)&x[(m0 + lm) * D_ + k0 + lk];
        xs[lk + 0][lm] = xv.x; xs[lk + 1][lm] = xv.y;
        xs[lk + 2][lm] = xv.z; xs[lk + 3][lm] = xv.w;
        #pragma unroll
        for (int w = 0; w < 3; w++) {
            float4 wv4 = *(const float4*)&wp[w][lm * D_ + k0 + lk];
            ws[w][lk + 0][lm] = wv4.x; ws[w][lk + 1][lm] = wv4.y;
            ws[w][lk + 2][lm] = wv4.z; ws[w][lk + 3][lm] = wv4.w;
        }
        __syncthreads();

        #pragma unroll
        for (int kk = 0; kk < 16; kk++) {
            float4 a = *(const float4*)&xs[kk][ty * 4];
            float4 b0 = *(const float4*)&ws[0][kk][tx * 4];
            float4 b1 = *(const float4*)&ws[1][kk][tx * 4];
            float4 b2 = *(const float4*)&ws[2][kk][tx * 4];
            fma4x4(acc[0], a, b0);
            fma4x4(acc[1], a, b1);
            fma4x4(acc[2], a, b2);
        }
    }

    const int bb = m0 / S_;
    const int s0 = m0 % S_;

    // Q and K: transposed epilogue -> [B][H][S]
    #pragma unroll
    for (int j = 0; j < 4; j++) {
        int h = tx * 4 + j;
        float bvq = bq[h];
        *(float4*)&g_qt[(bb * H_ + h) * S_ + s0 + ty * 4] =
            make_float4(acc[0][0][j] + bvq, acc[0][1][j] + bvq,
                        acc[0][2][j] + bvq, acc[0][3][j] + bvq);
        float bvk = bk[h];
        *(float4*)&g_kt[(bb * H_ + h) * S_ + s0 + ty * 4] =
            make_float4(acc[1][0][j] + bvk, acc[1][1][j] + bvk,
                        acc[1][2][j] + bvk, acc[1][3][j] + bvk);
    }
    // V: natural epilogue -> [B][S][H]
    float4 b4 = *(const float4*)&bv[tx * 4];
    #pragma unroll
    for (int i = 0; i < 4; i++) {
        *(float4*)&g_v[(m0 + ty * 4 + i) * H_ + tx * 4] =
            make_float4(acc[2][i][0] + b4.x, acc[2][i][1] + b4.y,
                        acc[2][i][2] + b4.z, acc[2][i][3] + b4.w);
    }
}

// ---------------------------------------------------------------------------
// Flash attention, causal, fp32, parity split-K.
// CTA (qt, j, b) processes key tiles kt = j, j+2, ... <= qt for query tile qt.
// 512 CTAs -> ~3 resident per SM (vs 1 before) to saturate the smem crossbar.
// Writes unnormalized O + (m, l) partials; combine kernel merges.
// qt = 63 - blockIdx.x so the longest (diagonal) jobs launch first.
// ---------------------------------------------------------------------------
__global__ __launch_bounds__(256) void attn_split(void)
{
    __shared__ float qs[64][64];   // [d][q]  (Q^T tile, pre-scaled)
    __shared__ float ks[64][64];   // [d][k]; reused as ps[q][k]
    __shared__ float vs[64][64];   // [k][h]
    float (*ps)[64] = ks;

    const int qt  = 63 - (int)blockIdx.x;
    const int j   = blockIdx.y;
    const int b   = blockIdx.z;
    const int tid = threadIdx.x;
    const int tx  = tid & 15;
    const int ty  = tid >> 4;
    const int lq  = tx * 4;
    const int lh  = ty;

    #pragma unroll
    for (int r = 0; r < 4; r++) {
        int h = lh + r * 16;
        float4 v = *(const float4*)&g_qt[(b * H_ + h) * S_ + qt * 64 + lq];
        v.x *= 0.125f; v.y *= 0.125f; v.z *= 0.125f; v.w *= 0.125f;
        *(float4*)&qs[h][lq] = v;
    }

    float o[4][4] = {};
    float m[4], l[4];
    #pragma unroll
    for (int i = 0; i < 4; i++) { m[i] = -3.0e38f; l[i] = 0.0f; }

    for (int kt = j; kt <= qt; kt += 2) {
        __syncthreads();   // prev iter's PV GEMM done; also orders qs store (1st iter)
        #pragma unroll
        for (int r = 0; r < 4; r++) {
            int h = lh + r * 16;
            *(float4*)&ks[h][lq] =
                *(const float4*)&g_kt[(b * H_ + h) * S_ + kt * 64 + lq];
            *(float4*)&vs[h][lq] =
                *(const float4*)&g_v[((b * S_) + kt * 64 + h) * H_ + lq];
        }
        __syncthreads();

        // GEMM1: s = (Q/8) K^T
        float s[4][4] = {};
        #pragma unroll 16
        for (int d = 0; d < 64; d++) {
            float4 a  = *(const float4*)&qs[d][ty * 4];
            float4 kb = *(const float4*)&ks[d][lq];
            fma4x4(s, a, kb);
        }

        if (kt == qt) {   // causal mask within diagonal tile
            #pragma unroll
            for (int i = 0; i < 4; i++)
                #pragma unroll
                for (int jj = 0; jj < 4; jj++)
                    if (lq + jj > ty * 4 + i) s[i][jj] = -1.0e30f;
        }

        __syncthreads();   // done reading ks -> reuse as ps

        // online softmax
        #pragma unroll
        for (int i = 0; i < 4; i++) {
            float mt = fmaxf(fmaxf(s[i][0], s[i][1]), fmaxf(s[i][2], s[i][3]));
            mt = fmaxf(mt, __shfl_xor_sync(0xffffffffu, mt, 1));
            mt = fmaxf(mt, __shfl_xor_sync(0xffffffffu, mt, 2));
            mt = fmaxf(mt, __shfl_xor_sync(0xffffffffu, mt, 4));
            mt = fmaxf(mt, __shfl_xor_sync(0xffffffffu, mt, 8));
            float mnew  = fmaxf(m[i], mt);
            float alpha = __expf(m[i] - mnew);
            m[i] = mnew;
            float rs = 0.0f;
            #pragma unroll
            for (int jj = 0; jj < 4; jj++) {
                float p = __expf(s[i][jj] - mnew);
                s[i][jj] = p;
                rs += p;
            }
            rs += __shfl_xor_sync(0xffffffffu, rs, 1);
            rs += __shfl_xor_sync(0xffffffffu, rs, 2);
            rs += __shfl_xor_sync(0xffffffffu, rs, 4);
            rs += __shfl_xor_sync(0xffffffffu, rs, 8);
            l[i] = l[i] * alpha + rs;
            #pragma unroll
            for (int jj = 0; jj < 4; jj++) o[i][jj] *= alpha;
            *(float4*)&ps[ty * 4 + i][lq] =
                make_float4(s[i][0], s[i][1], s[i][2], s[i][3]);
        }
        __syncthreads();

        // GEMM2: O += P V
        #pragma unroll 16
        for (int kk = 0; kk < 64; kk++) {
            float a0 = ps[ty * 4 + 0][kk];
            float a1 = ps[ty * 4 + 1][kk];
            float a2 = ps[ty * 4 + 2][kk];
            float a3 = ps[ty * 4 + 3][kk];
            float4 vv = *(const float4*)&vs[kk][lq];
            o[0][0] += a0 * vv.x; o[0][1] += a0 * vv.y; o[0][2] += a0 * vv.z; o[0][3] += a0 * vv.w;
            o[1][0] += a1 * vv.x; o[1][1] += a1 * vv.y; o[1][2] += a1 * vv.z; o[1][3] += a1 * vv.w;
            o[2][0] += a2 * vv.x; o[2][1] += a2 * vv.y; o[2][2] += a2 * vv.z; o[2][3] += a2 * vv.w;
            o[3][0] += a3 * vv.x; o[3][1] += a3 * vv.y; o[3][2] += a3 * vv.z; o[3][3] += a3 * vv.w;
        }
    }

    // write partials (unnormalized O, plus m and l per row)
    const int prow = (j * B_ + b) * S_ + qt * 64;
    #pragma unroll
    for (int i = 0; i < 4; i++) {
        *(float4*)&g_op[(prow + ty * 4 + i) * H_ + lq] =
            make_float4(o[i][0], o[i][1], o[i][2], o[i][3]);
        if (tx == 0) {
            g_mp[prow + ty * 4 + i] = m[i];
            g_lp[prow + ty * 4 + i] = l[i];
        }
    }
}

// ---------------------------------------------------------------------------
// Merge the two split-K partials: out = (w1*O1 + w2*O2) / (w1*l1 + w2*l2),
// w_j = exp(m_j - max(m1,m2)). Empty partial (m=-3e38, l=0) contributes 0.
// One float4 per thread: 262144 float4s.
// ---------------------------------------------------------------------------
__global__ __launch_bounds__(256) void attn_combine(float* __restrict__ out)
{
    const int idx = blockIdx.x * 256 + threadIdx.x;      // float4 index
    const int row = idx >> 4;                            // H_/4 = 16 float4 per row
    const int half2 = B_ * S_;

    float m1 = g_mp[row],         l1 = g_lp[row];
    float m2 = g_mp[half2 + row], l2 = g_lp[half2 + row];
    float M  = fmaxf(m1, m2);
    float w1 = __expf(m1 - M);
    float w2 = __expf(m2 - M);
    float inv = 1.0f / (w1 * l1 + w2 * l2);

    const float4* o1p = (const float4*)g_op;
    float4 o1 = o1p[idx];
    float4 o2 = o1p[(size_t)half2 * 16 + idx];

    float4 r;
    r.x = (w1 * o1.x + w2 * o2.x) * inv;
    r.y = (w1 * o1.y + w2 * o2.y) * inv;
    r.z = (w1 * o1.z + w2 * o2.z) * inv;
    r.w = (w1 * o1.w + w2 * o2.w) * inv;
    ((float4*)out)[idx] = r;
}

extern "C" void kernel_launch(void* const* d_in, const int* in_sizes, int n_in,
                              void* d_out, int out_size)
{
    (void)in_sizes; (void)n_in; (void)out_size;
    const float* x  = (const float*)d_in[0];
    const float* wq = (const float*)d_in[1];
    const float* bq = (const float*)d_in[2];
    const float* wk = (const float*)d_in[3];
    const float* bk = (const float*)d_in[4];
    const float* wv = (const float*)d_in[5];
    const float* bv = (const float*)d_in[6];
    float* out = (float*)d_out;

    qkv_proj_fused<<<dim3((B_ * S_) / 64, 1, 1), 256>>>(x, wq, bq, wk, bk, wv, bv);
    attn_split<<<dim3(64, 2, B_), 256>>>();
    attn_combine<<<(B_ * S_ * H_ / 4) / 256, 256>>>(out);
}